// round 6
// baseline (speedup 1.0000x reference)
#include <cuda_runtime.h>

// ---------------------------------------------------------------------------
// SparseConvolutionDownsample: rulebook sparse conv + BN + LeakyReLU
//   feats [1048576, 64] f32, W [4, 64, 128] f32, gamma/beta [128] f32,
//   in_idx/out_idx [4, 262144] i32, out [262144, 128] f32
// ---------------------------------------------------------------------------

namespace {
constexpr int C_IN   = 64;
constexpr int C_OUT  = 128;
constexpr int PNUM   = 262144;
constexpr int N_OUTR = 262144;
constexpr float BN_EPS = 1e-4f;
constexpr float LEAK   = 0.333f;

constexpr int GRIDX    = 114;                 // 114*4 warps = 456 = 2*228
constexpr int P_STRIDE = 228;                 // row-warps per (k, half)
constexpr int NUM_T    = (PNUM + P_STRIDE - 1) / P_STRIDE;  // 1150
constexpr int NUM_B    = (NUM_T + 3) / 4;     // 288 batches of 4 rows
}

// per-channel running sums: [0..127] = sum, [128..255] = sum of squares
__device__ float g_stats[2 * C_OUT];

// packed f32x2 ops — PTX-only on sm_103a
__device__ __forceinline__ void ffma2(unsigned long long& d,
                                      unsigned long long a,
                                      unsigned long long b) {
    asm("fma.rn.f32x2 %0, %1, %2, %0;" : "+l"(d) : "l"(a), "l"(b));
}
__device__ __forceinline__ unsigned long long add2(unsigned long long a,
                                                   unsigned long long b) {
    unsigned long long d;
    asm("add.rn.f32x2 %0, %1, %2;" : "=l"(d) : "l"(a), "l"(b));
    return d;
}
__device__ __forceinline__ unsigned long long pack2(float x, float y) {
    return ((unsigned long long)__float_as_uint(y) << 32)
         |  (unsigned long long)__float_as_uint(x);
}
__device__ __forceinline__ float lo32(unsigned long long v) {
    return __uint_as_float((unsigned)(v & 0xffffffffu));
}
__device__ __forceinline__ float hi32(unsigned long long v) {
    return __uint_as_float((unsigned)(v >> 32));
}

// ---------------------------------------------------------------------------
// Kernel 0: zero the accumulator + zero BN stats
// ---------------------------------------------------------------------------
__global__ void zero_kernel(float4* __restrict__ out) {
    const size_t n = (size_t)N_OUTR * C_OUT / 4;
    const size_t stride = (size_t)gridDim.x * blockDim.x;
    const float4 z = make_float4(0.f, 0.f, 0.f, 0.f);
    for (size_t i = (size_t)blockIdx.x * blockDim.x + threadIdx.x; i < n; i += stride)
        out[i] = z;
    if (blockIdx.x == 0 && threadIdx.x < 2 * C_OUT)
        g_stats[threadIdx.x] = 0.f;
}

// no-op launch-slot filler: aligns ncu's "-s 5 -c 1" onto spconv_kernel
__global__ void nop_kernel() {}

// ---------------------------------------------------------------------------
// Kernel 1: warp-autonomous cp.async gather -> GEMV -> v4-atomic scatter
//
// Occupancy push: __launch_bounds__(128,3) -> 12 warps/SM (3/SMSP).
// Gather now uses cp.async (LDGSTS, 8B/lane, zero-fill for OOB rows) into a
// per-warp double-buffered SMEM ring — no register staging of features.
// Compute per row unchanged: 16 LDS.128 + 64 FFMA2 on 4 K-pair-packed chains,
// add.rn.f32x2 fold, lane-pair SHFLs, even lanes issue red.global.add.v4.f32.
// ---------------------------------------------------------------------------
__global__ __launch_bounds__(128, 3) void spconv_kernel(
    const float* __restrict__ feats,
    const float* __restrict__ W,
    const int*   __restrict__ in_idx,
    const int*   __restrict__ out_idx,
    float*       __restrict__ out)
{
    // [warp][buf][row-in-batch][lane]: raw pair {f[2*lane], f[2*lane+1]} (8 KB)
    __shared__ __align__(16) unsigned long long sfeat[4][2][4][32];

    const int k    = blockIdx.y;
    const int w    = threadIdx.x >> 5;
    const int lane = threadIdx.x & 31;
    const int gw   = blockIdx.x * 4 + w;     // 0..455
    const int half = gw & 1;
    const int p0   = gw >> 1;                // 0..227
    const int chBase = half * 64 + 2 * lane;

    unsigned sbase;
    asm("{ .reg .u64 t; cvta.to.shared.u64 t, %1; cvt.u32.u64 %0, t; }"
        : "=r"(sbase) : "l"(&sfeat[0][0][0][0]));

    // ---- W[k] columns chBase, chBase+1 -> K-pair-packed registers ----
    const float* Wk = W + k * C_IN * C_OUT;
    unsigned long long w0[C_IN / 2], w1[C_IN / 2];
#pragma unroll
    for (int j = 0; j < C_IN / 2; j++) {
        float2 wa = *reinterpret_cast<const float2*>(Wk + (2 * j)     * C_OUT + chBase);
        float2 wb = *reinterpret_cast<const float2*>(Wk + (2 * j + 1) * C_OUT + chBase);
        w0[j] = pack2(wa.x, wb.x);
        w1[j] = pack2(wa.y, wb.y);
    }

    const int* inI  = in_idx  + k * PNUM;
    const int* outI = out_idx + k * PNUM;

    // issue one 4-row gather batch into buffer `buf`; returns out-row ids
    auto load_batch = [&](int buf, int tBase, int* on) {
#pragma unroll
        for (int u = 0; u < 4; u++) {
            int p  = p0 + (tBase + u) * P_STRIDE;
            int pc = (p < PNUM) ? p : (PNUM - 1);
            int ii = __ldg(&inI[pc]);
            on[u]  = __ldg(&outI[pc]);
            const float* src = feats + (size_t)ii * C_IN + 2 * lane;
            unsigned dst = sbase + (unsigned)((((w * 2 + buf) * 4 + u) * 32 + lane) * 8);
            unsigned sz  = (p < PNUM) ? 8u : 0u;   // 0 => zero-fill
            asm volatile("cp.async.ca.shared.global [%0], [%1], 8, %2;"
                         :: "r"(dst), "l"(src), "r"(sz));
        }
        asm volatile("cp.async.commit_group;" ::: "memory");
    };

    int ocur[4], onext[4];
    load_batch(0, 0, onext);

    for (int b = 0; b < NUM_B; b++) {
#pragma unroll
        for (int u = 0; u < 4; u++) ocur[u] = onext[u];

        // issue batch b+1 into the other buffer (past-end batches zero-fill)
        load_batch((b + 1) & 1, 4 * (b + 1), onext);

        // wait for batch b (one group still in flight), make it warp-visible
        asm volatile("cp.async.wait_group 1;" ::: "memory");
        __syncwarp();

        // compute the 4 staged rows of batch b
#pragma unroll
        for (int u = 0; u < 4; u++) {
            const int p = p0 + (4 * b + u) * P_STRIDE;
            const ulonglong2* sf =
                reinterpret_cast<const ulonglong2*>(&sfeat[w][b & 1][u][0]);
            unsigned long long a00 = 0ull, a01 = 0ull, a10 = 0ull, a11 = 0ull;
#pragma unroll
            for (int t = 0; t < 16; t++) {
                ulonglong2 q = sf[t];          // {f[4t..4t+1]}, {f[4t+2..4t+3]}
                ffma2(a00, q.x, w0[2 * t]);
                ffma2(a10, q.x, w1[2 * t]);
                ffma2(a01, q.y, w0[2 * t + 1]);
                ffma2(a11, q.y, w1[2 * t + 1]);
            }
            unsigned long long s0 = add2(a00, a01);
            unsigned long long s1 = add2(a10, a11);
            float r0 = lo32(s0) + hi32(s0);    // channel chBase
            float r1 = lo32(s1) + hi32(s1);    // channel chBase+1

            float r2 = __shfl_down_sync(0xffffffffu, r0, 1);
            float r3 = __shfl_down_sync(0xffffffffu, r1, 1);
            if (((lane & 1) == 0) && p < PNUM) {
                float* addr = out + (size_t)ocur[u] * C_OUT + chBase;
                asm volatile("red.global.add.v4.f32 [%0], {%1, %2, %3, %4};"
                             :: "l"(addr), "f"(r0), "f"(r1), "f"(r2), "f"(r3)
                             : "memory");
            }
        }
        __syncwarp();   // all lanes done with buf (b&1) before it is re-filled
    }
}

// ---------------------------------------------------------------------------
// Kernel 2: per-channel sum / sumsq (block-partial + global atomics)
// ---------------------------------------------------------------------------
__global__ void bn_stats_kernel(const float4* __restrict__ out) {
    const int cg = threadIdx.x & 31;   // float4 channel group
    const int rs = threadIdx.x >> 5;   // row sub-slot 0..7
    const int rowsPerBlock = N_OUTR / gridDim.x;
    const int r0 = blockIdx.x * rowsPerBlock;

    float4 s  = make_float4(0.f, 0.f, 0.f, 0.f);
    float4 s2 = make_float4(0.f, 0.f, 0.f, 0.f);
    for (int r = r0 + rs; r < r0 + rowsPerBlock; r += 8) {
        float4 vv = out[(size_t)r * (C_OUT / 4) + cg];
        s.x += vv.x;  s.y += vv.y;  s.z += vv.z;  s.w += vv.w;
        s2.x += vv.x * vv.x;  s2.y += vv.y * vv.y;
        s2.z += vv.z * vv.z;  s2.w += vv.w * vv.w;
    }

    __shared__ float4 shs[256], shq[256];
    shs[threadIdx.x] = s;
    shq[threadIdx.x] = s2;
    __syncthreads();
#pragma unroll
    for (int off = 128; off >= 32; off >>= 1) {
        if (threadIdx.x < off) {
            float4 a = shs[threadIdx.x], b = shs[threadIdx.x + off];
            a.x += b.x; a.y += b.y; a.z += b.z; a.w += b.w;
            shs[threadIdx.x] = a;
            float4 c = shq[threadIdx.x], d = shq[threadIdx.x + off];
            c.x += d.x; c.y += d.y; c.z += d.z; c.w += d.w;
            shq[threadIdx.x] = c;
        }
        __syncthreads();
    }
    if (threadIdx.x < 32) {
        float4 a = shs[threadIdx.x], c = shq[threadIdx.x];
        int c0 = threadIdx.x * 4;
        atomicAdd(&g_stats[c0 + 0], a.x);
        atomicAdd(&g_stats[c0 + 1], a.y);
        atomicAdd(&g_stats[c0 + 2], a.z);
        atomicAdd(&g_stats[c0 + 3], a.w);
        atomicAdd(&g_stats[C_OUT + c0 + 0], c.x);
        atomicAdd(&g_stats[C_OUT + c0 + 1], c.y);
        atomicAdd(&g_stats[C_OUT + c0 + 2], c.z);
        atomicAdd(&g_stats[C_OUT + c0 + 3], c.w);
    }
}

// ---------------------------------------------------------------------------
// Kernel 3: normalize + LeakyReLU (in place, float4)
// ---------------------------------------------------------------------------
__global__ void bn_norm_kernel(float4* __restrict__ out,
                               const float* __restrict__ gamma,
                               const float* __restrict__ beta) {
    __shared__ float sc[C_OUT], sf[C_OUT];
    if (threadIdx.x < C_OUT) {
        int c = threadIdx.x;
        const float inv = 1.f / (float)N_OUTR;
        float mean = g_stats[c] * inv;
        float var  = g_stats[C_OUT + c] * inv - mean * mean;
        float s    = gamma[c] * rsqrtf(var + BN_EPS);
        sc[c] = s;
        sf[c] = beta[c] - mean * s;
    }
    __syncthreads();

    const size_t n = (size_t)N_OUTR * (C_OUT / 4);
    const size_t stride = (size_t)gridDim.x * blockDim.x;
    for (size_t i = (size_t)blockIdx.x * blockDim.x + threadIdx.x; i < n; i += stride) {
        int c0 = ((int)(i & 31)) * 4;
        float4 v = out[i];
        v.x = v.x * sc[c0 + 0] + sf[c0 + 0];
        v.y = v.y * sc[c0 + 1] + sf[c0 + 1];
        v.z = v.z * sc[c0 + 2] + sf[c0 + 2];
        v.w = v.w * sc[c0 + 3] + sf[c0 + 3];
        v.x = (v.x >= 0.f) ? v.x : v.x * LEAK;
        v.y = (v.y >= 0.f) ? v.y : v.y * LEAK;
        v.z = (v.z >= 0.f) ? v.z : v.z * LEAK;
        v.w = (v.w >= 0.f) ? v.w : v.w * LEAK;
        out[i] = v;
    }
}

// ---------------------------------------------------------------------------
// Launch: inputs per metadata order:
//   0 feats, 1 W, 2 gamma, 3 beta, 4 in_idx, 5 out_idx, 6 n_out (ignored)
// ---------------------------------------------------------------------------
extern "C" void kernel_launch(void* const* d_in, const int* in_sizes, int n_in,
                              void* d_out, int out_size) {
    const float* feats   = (const float*)d_in[0];
    const float* W       = (const float*)d_in[1];
    const float* gamma   = (const float*)d_in[2];
    const float* beta    = (const float*)d_in[3];
    const int*   in_idx  = (const int*)d_in[4];
    const int*   out_idx = (const int*)d_in[5];
    float* out = (float*)d_out;

    zero_kernel<<<1024, 256>>>((float4*)out);
    nop_kernel<<<1, 32>>>();
    nop_kernel<<<1, 32>>>();
    spconv_kernel<<<dim3(GRIDX, 4), 128>>>(feats, W, in_idx, out_idx, out);
    bn_stats_kernel<<<256, 256>>>((const float4*)out);
    bn_norm_kernel<<<1024, 256>>>((float4*)out, gamma, beta);
}